// round 1
// baseline (speedup 1.0000x reference)
#include <cuda_runtime.h>

// RNN_33964601377372: h_{t+1} = relu(x_t*W_ih + b_ih + b_hh + W_hh h_t), out = fc(h_T)
// Layout: one batch element per quad of 4 lanes; each lane owns 5 of the 20
// hidden rows with its 5x20 W_hh slice in registers. Per-step h exchange via
// 20 width-4 shuffles. x prefetched as float4 (T divisible by 4 for T=1000;
// scalar tail kept for safety).

#define HID 20
#define RPT 5   // rows per thread
#define QUAD 4  // threads per batch element

__global__ __launch_bounds__(64) void rnn_fused_kernel(
    const float* __restrict__ x,    // [B, T]
    const float* __restrict__ Wih,  // [H]
    const float* __restrict__ Whh,  // [H, H] row-major
    const float* __restrict__ bih,  // [H]
    const float* __restrict__ bhh,  // [H]
    const float* __restrict__ fcw,  // [H]
    const float* __restrict__ fcb,  // [1]
    float* __restrict__ out,        // [B]
    int B, int T)
{
    int tid = blockIdx.x * blockDim.x + threadIdx.x;
    int batch = tid >> 2;
    int q = tid & 3;  // lane within quad: owns rows q*5 .. q*5+4
    if (batch >= B) return;
    const int r0 = q * RPT;

    // Per-lane weight slice in registers (fully unrolled -> no local memory).
    float w[RPT][HID];
#pragma unroll
    for (int r = 0; r < RPT; ++r)
#pragma unroll
        for (int j = 0; j < HID; ++j)
            w[r][j] = Whh[(r0 + r) * HID + j];

    float wih[RPT], bias[RPT], fw[RPT], h[RPT];
#pragma unroll
    for (int r = 0; r < RPT; ++r) {
        wih[r]  = Wih[r0 + r];
        bias[r] = bih[r0 + r] + bhh[r0 + r];
        fw[r]   = fcw[r0 + r];
        h[r]    = 0.0f;
    }

    const float* xb = x + (size_t)batch * T;  // row start: T*4=4000B, 16B-aligned
    const float4* xb4 = (const float4*)xb;
    const int nChunks = T >> 2;

    float4 xv = (nChunks > 0) ? xb4[0] : make_float4(0.f, 0.f, 0.f, 0.f);
    float4 xnext = xv;

    for (int c = 0; c < nChunks; ++c) {
        if (c + 1 < nChunks) xnext = xb4[c + 1];  // prefetch: 4 steps of hiding
#pragma unroll
        for (int s = 0; s < 4; ++s) {
            float xt = (s == 0) ? xv.x : (s == 1) ? xv.y : (s == 2) ? xv.z : xv.w;
            float acc[RPT];
#pragma unroll
            for (int r = 0; r < RPT; ++r) acc[r] = fmaf(xt, wih[r], bias[r]);
#pragma unroll
            for (int j = 0; j < HID; ++j) {
                // h_j lives in register (j%5) of quad-lane (j/5); both const after unroll
                float hj = __shfl_sync(0xffffffffu, h[j % RPT], j / RPT, QUAD);
#pragma unroll
                for (int r = 0; r < RPT; ++r) acc[r] = fmaf(hj, w[r][j], acc[r]);
            }
#pragma unroll
            for (int r = 0; r < RPT; ++r) h[r] = fmaxf(acc[r], 0.0f);
        }
        xv = xnext;
    }

    // Scalar tail (not taken for T=1000).
    for (int t = nChunks << 2; t < T; ++t) {
        float xt = xb[t];
        float acc[RPT];
#pragma unroll
        for (int r = 0; r < RPT; ++r) acc[r] = fmaf(xt, wih[r], bias[r]);
#pragma unroll
        for (int j = 0; j < HID; ++j) {
            float hj = __shfl_sync(0xffffffffu, h[j % RPT], j / RPT, QUAD);
#pragma unroll
            for (int r = 0; r < RPT; ++r) acc[r] = fmaf(hj, w[r][j], acc[r]);
        }
#pragma unroll
        for (int r = 0; r < RPT; ++r) h[r] = fmaxf(acc[r], 0.0f);
    }

    // Head: out[b] = h . fc_w + fc_b ; quad butterfly reduction.
    float p = 0.0f;
#pragma unroll
    for (int r = 0; r < RPT; ++r) p = fmaf(h[r], fw[r], p);
    p += __shfl_xor_sync(0xffffffffu, p, 1, QUAD);
    p += __shfl_xor_sync(0xffffffffu, p, 2, QUAD);
    if (q == 0) out[batch] = p + fcb[0];
}

extern "C" void kernel_launch(void* const* d_in, const int* in_sizes, int n_in,
                              void* d_out, int out_size)
{
    const float* x    = (const float*)d_in[0];
    const float* Wih  = (const float*)d_in[1];
    const float* Whh  = (const float*)d_in[2];
    const float* bih  = (const float*)d_in[3];
    const float* bhh  = (const float*)d_in[4];
    const float* fcw  = (const float*)d_in[5];
    const float* fcb  = (const float*)d_in[6];
    float* out = (float*)d_out;

    int B = out_size;               // one output per batch element
    int T = in_sizes[0] / B;        // x has B*T elements

    int threads = 64;               // 16 batches per CTA -> 256 CTAs at B=4096
    int total = B * QUAD;
    int blocks = (total + threads - 1) / threads;
    rnn_fused_kernel<<<blocks, threads>>>(x, Wih, Whh, bih, bhh, fcw, fcb, out, B, T);
}

// round 2
// speedup vs baseline: 1.0278x; 1.0278x over previous
#include <cuda_runtime.h>

// RNN_33964601377372: h_{t+1} = relu(x_t*W_ih + b_ih + b_hh + W_hh h_t), out = fc(h_T)
// Quad layout (4 lanes per batch, 5 rows/lane) + packed fp32x2 row-pairs:
// rows (r0,r0+1) and (r0+2,r0+3) run as fma.rn.f32x2 chains, row r0+4 scalar.
// Per step: 20 width-4 shuffles (scalar h_j) + 20 dup-MOVs + 40 FFMA2 + 20 FFMA.

#define HID 20
#define RPT 5
#define QUAD 4

typedef unsigned long long u64;

__device__ __forceinline__ u64 pack2(float lo, float hi) {
    u64 r;
    asm("mov.b64 %0, {%1, %2};" : "=l"(r) : "f"(lo), "f"(hi));
    return r;
}
__device__ __forceinline__ u64 dup2(float v) {
    u64 r;
    asm("mov.b64 %0, {%1, %1};" : "=l"(r) : "f"(v));
    return r;
}
__device__ __forceinline__ void unpack2(u64 p, float& lo, float& hi) {
    asm("mov.b64 {%0, %1}, %2;" : "=f"(lo), "=f"(hi) : "l"(p));
}
__device__ __forceinline__ u64 ffma2(u64 a, u64 b, u64 c) {
    u64 d;
    asm("fma.rn.f32x2 %0, %1, %2, %3;" : "=l"(d) : "l"(a), "l"(b), "l"(c));
    return d;
}

__global__ __launch_bounds__(64) void rnn_fused_kernel(
    const float* __restrict__ x,    // [B, T]
    const float* __restrict__ Wih,  // [H]
    const float* __restrict__ Whh,  // [H, H] row-major
    const float* __restrict__ bih,  // [H]
    const float* __restrict__ bhh,  // [H]
    const float* __restrict__ fcw,  // [H]
    const float* __restrict__ fcb,  // [1]
    float* __restrict__ out,        // [B]
    int B, int T)
{
    int tid = blockIdx.x * blockDim.x + threadIdx.x;
    int batch = tid >> 2;
    int q = tid & 3;  // lane within quad: owns rows q*5 .. q*5+4
    if (batch >= B) return;
    const int r0 = q * RPT;

    // Packed weight chains: rows (r0,r0+1) -> A, (r0+2,r0+3) -> B, r0+4 -> scalar C.
    u64 wA[HID], wB[HID];
    float wC[HID];
#pragma unroll
    for (int j = 0; j < HID; ++j) {
        wA[j] = pack2(Whh[(r0 + 0) * HID + j], Whh[(r0 + 1) * HID + j]);
        wB[j] = pack2(Whh[(r0 + 2) * HID + j], Whh[(r0 + 3) * HID + j]);
        wC[j] = Whh[(r0 + 4) * HID + j];
    }

    u64 wihA = pack2(Wih[r0 + 0], Wih[r0 + 1]);
    u64 wihB = pack2(Wih[r0 + 2], Wih[r0 + 3]);
    float wihC = Wih[r0 + 4];
    u64 biasA = pack2(bih[r0 + 0] + bhh[r0 + 0], bih[r0 + 1] + bhh[r0 + 1]);
    u64 biasB = pack2(bih[r0 + 2] + bhh[r0 + 2], bih[r0 + 3] + bhh[r0 + 3]);
    float biasC = bih[r0 + 4] + bhh[r0 + 4];

    float h[RPT];
#pragma unroll
    for (int r = 0; r < RPT; ++r) h[r] = 0.0f;

    const float* xb = x + (size_t)batch * T;  // 4000B row stride, 16B-aligned
    const float4* xb4 = (const float4*)xb;
    const int nChunks = T >> 2;

    float4 xv = (nChunks > 0) ? xb4[0] : make_float4(0.f, 0.f, 0.f, 0.f);
    float4 xnext = xv;

    for (int c = 0; c < nChunks; ++c) {
        if (c + 1 < nChunks) xnext = xb4[c + 1];  // 4 steps of load hiding
#pragma unroll
        for (int s = 0; s < 4; ++s) {
            float xt = (s == 0) ? xv.x : (s == 1) ? xv.y : (s == 2) ? xv.z : xv.w;
            u64 xt2 = dup2(xt);
            u64 accA = ffma2(xt2, wihA, biasA);
            u64 accB = ffma2(xt2, wihB, biasB);
            float accC = fmaf(xt, wihC, biasC);
#pragma unroll
            for (int j = 0; j < HID; ++j) {
                float hj = __shfl_sync(0xffffffffu, h[j % RPT], j / RPT, QUAD);
                u64 hj2 = dup2(hj);
                accA = ffma2(hj2, wA[j], accA);
                accB = ffma2(hj2, wB[j], accB);
                accC = fmaf(hj, wC[j], accC);
            }
            float a0, a1, a2, a3;
            unpack2(accA, a0, a1);
            unpack2(accB, a2, a3);
            h[0] = fmaxf(a0, 0.0f);
            h[1] = fmaxf(a1, 0.0f);
            h[2] = fmaxf(a2, 0.0f);
            h[3] = fmaxf(a3, 0.0f);
            h[4] = fmaxf(accC, 0.0f);
        }
        xv = xnext;
    }

    // Scalar tail (not taken for T=1000).
    for (int t = nChunks << 2; t < T; ++t) {
        float xt = xb[t];
        u64 xt2 = dup2(xt);
        u64 accA = ffma2(xt2, wihA, biasA);
        u64 accB = ffma2(xt2, wihB, biasB);
        float accC = fmaf(xt, wihC, biasC);
#pragma unroll
        for (int j = 0; j < HID; ++j) {
            float hj = __shfl_sync(0xffffffffu, h[j % RPT], j / RPT, QUAD);
            u64 hj2 = dup2(hj);
            accA = ffma2(hj2, wA[j], accA);
            accB = ffma2(hj2, wB[j], accB);
            accC = fmaf(hj, wC[j], accC);
        }
        float a0, a1, a2, a3;
        unpack2(accA, a0, a1);
        unpack2(accB, a2, a3);
        h[0] = fmaxf(a0, 0.0f);
        h[1] = fmaxf(a1, 0.0f);
        h[2] = fmaxf(a2, 0.0f);
        h[3] = fmaxf(a3, 0.0f);
        h[4] = fmaxf(accC, 0.0f);
    }

    // Head: out[b] = h . fc_w + fc_b ; quad butterfly reduction.
    float fw[RPT];
#pragma unroll
    for (int r = 0; r < RPT; ++r) fw[r] = fcw[r0 + r];
    float p = 0.0f;
#pragma unroll
    for (int r = 0; r < RPT; ++r) p = fmaf(h[r], fw[r], p);
    p += __shfl_xor_sync(0xffffffffu, p, 1, QUAD);
    p += __shfl_xor_sync(0xffffffffu, p, 2, QUAD);
    if (q == 0) out[batch] = p + fcb[0];
}

extern "C" void kernel_launch(void* const* d_in, const int* in_sizes, int n_in,
                              void* d_out, int out_size)
{
    const float* x    = (const float*)d_in[0];
    const float* Wih  = (const float*)d_in[1];
    const float* Whh  = (const float*)d_in[2];
    const float* bih  = (const float*)d_in[3];
    const float* bhh  = (const float*)d_in[4];
    const float* fcw  = (const float*)d_in[5];
    const float* fcb  = (const float*)d_in[6];
    float* out = (float*)d_out;

    int B = out_size;
    int T = in_sizes[0] / B;

    int threads = 64;
    int total = B * QUAD;
    int blocks = (total + threads - 1) / threads;
    rnn_fused_kernel<<<blocks, threads>>>(x, Wih, Whh, bih, bhh, fcw, fcb, out, B, T);
}